// round 1
// baseline (speedup 1.0000x reference)
#include <cuda_runtime.h>

#define H_LR 512
#define W_LR 512
#define H_HR 2048
#define W_HR 2048
#define PLANES 12
#define EPS_F 0.01f

// Scratch for mean_A / mean_b at low resolution (alloc-free: __device__ globals)
__device__ float g_meanA[PLANES * H_LR * W_LR];
__device__ float g_meanB[PLANES * H_LR * W_LR];

#define TILE 32
#define SM_W 36   // TILE + 4 (2-pixel halo each side for double 3x3)
#define SM_A 34   // TILE + 2 (1-pixel apron of A/b)
#define SSTR 37   // row stride, avoids bank conflicts

__global__ __launch_bounds__(256)
void k1_ab_mean(const float* __restrict__ x, const float* __restrict__ y) {
    __shared__ float sx[SM_W * SSTR];
    __shared__ float sy[SM_W * SSTR];
    __shared__ float sA[SM_A * SSTR];
    __shared__ float sB[SM_A * SSTR];

    const int plane = blockIdx.z;
    const int gy0 = blockIdx.y * TILE;
    const int gx0 = blockIdx.x * TILE;
    const float* __restrict__ xp = x + (size_t)plane * (H_LR * W_LR);
    const float* __restrict__ yp = y + (size_t)plane * (H_LR * W_LR);
    const int t = threadIdx.y * 32 + threadIdx.x;

    // Phase 1: load 36x36 halo with edge clamp
    for (int idx = t; idx < SM_W * SM_W; idx += 256) {
        int i = idx / SM_W, j = idx - i * SM_W;
        int gy = min(max(gy0 - 2 + i, 0), H_LR - 1);
        int gx = min(max(gx0 - 2 + j, 0), W_LR - 1);
        float xv = xp[gy * W_LR + gx];
        float yv = yp[gy * W_LR + gx];
        sx[i * SSTR + j] = xv;
        sy[i * SSTR + j] = yv;
    }
    __syncthreads();

    // Phase 2: compute A, b on the 34x34 apron.
    // A/b are evaluated at CLAMPED global pixel coords (replication padding of
    // A for the second boxfilter), while the inner 3x3 box over x/y uses the
    // true (also clamped) x coordinates.
    const float inv9 = 1.0f / 9.0f;
    for (int idx = t; idx < SM_A * SM_A; idx += 256) {
        int i = idx / SM_A, j = idx - i * SM_A;
        int py = min(max(gy0 - 1 + i, 0), H_LR - 1);
        int px = min(max(gx0 - 1 + j, 0), W_LR - 1);
        int si = py - gy0 + 2;   // in [1, 34]
        int sj = px - gx0 + 2;
        float sxs = 0.f, sys = 0.f, sxy = 0.f, sxx = 0.f;
        #pragma unroll
        for (int di = -1; di <= 1; di++) {
            #pragma unroll
            for (int dj = -1; dj <= 1; dj++) {
                float xv = sx[(si + di) * SSTR + (sj + dj)];
                float yv = sy[(si + di) * SSTR + (sj + dj)];
                sxs += xv;
                sys += yv;
                sxy += xv * yv;
                sxx += xv * xv;
            }
        }
        float mx = sxs * inv9;
        float my = sys * inv9;
        float cov = sxy * inv9 - mx * my;
        float var = sxx * inv9 - mx * mx;
        float A = cov / (var + EPS_F);
        float B = my - A * mx;
        sA[i * SSTR + j] = A;
        sB[i * SSTR + j] = B;
    }
    __syncthreads();

    // Phase 3: 3x3 box over A/b -> mean_A, mean_b, write to scratch
    const int tx = threadIdx.x;
    for (int ty = threadIdx.y; ty < TILE; ty += 8) {
        float sa = 0.f, sb = 0.f;
        #pragma unroll
        for (int di = 0; di < 3; di++) {
            #pragma unroll
            for (int dj = 0; dj < 3; dj++) {
                sa += sA[(ty + di) * SSTR + (tx + dj)];
                sb += sB[(ty + di) * SSTR + (tx + dj)];
            }
        }
        int o = plane * (H_LR * W_LR) + (gy0 + ty) * W_LR + (gx0 + tx);
        g_meanA[o] = sa * inv9;
        g_meanB[o] = sb * inv9;
    }
}

// Kernel 2: bilinear upsample (align_corners) of mean_A/mean_b + affine + clip.
// One thread -> 4 consecutive output pixels (float4 load/store of x_hr/out).
// 4 consecutive positions span 3*scale < 1 low-res unit -> only 3 columns needed.
__global__ __launch_bounds__(256)
void k2_upsample_apply(const float* __restrict__ xhr, float* __restrict__ out) {
    const float SCALE = 511.0f / 2047.0f;
    const int plane = blockIdx.z;
    const int oy = blockIdx.y;
    const int qx = blockIdx.x * blockDim.x + threadIdx.x;  // 0..511
    const int ox0 = qx * 4;

    float posy = (float)oy * SCALE;
    int iy0 = (int)posy;
    float tyf = posy - (float)iy0;
    int iy1 = min(iy0 + 1, H_LR - 1);

    float posx0 = (float)ox0 * SCALE;
    int jb = (int)posx0;
    int j1 = min(jb + 1, W_LR - 1);
    int j2 = min(jb + 2, W_LR - 1);

    const float* __restrict__ pA = g_meanA + (size_t)plane * (H_LR * W_LR);
    const float* __restrict__ pB = g_meanB + (size_t)plane * (H_LR * W_LR);
    const float* __restrict__ rA0 = pA + iy0 * W_LR;
    const float* __restrict__ rA1 = pA + iy1 * W_LR;
    const float* __restrict__ rB0 = pB + iy0 * W_LR;
    const float* __restrict__ rB1 = pB + iy1 * W_LR;

    float a00 = rA0[jb], a01 = rA0[j1], a02 = rA0[j2];
    float a10 = rA1[jb], a11 = rA1[j1], a12 = rA1[j2];
    float b00 = rB0[jb], b01 = rB0[j1], b02 = rB0[j2];
    float b10 = rB1[jb], b11 = rB1[j1], b12 = rB1[j2];

    // vertical lerp for the 3 columns
    float Ac0 = fmaf(tyf, a10 - a00, a00);
    float Ac1 = fmaf(tyf, a11 - a01, a01);
    float Ac2 = fmaf(tyf, a12 - a02, a02);
    float Bc0 = fmaf(tyf, b10 - b00, b00);
    float Bc1 = fmaf(tyf, b11 - b01, b01);
    float Bc2 = fmaf(tyf, b12 - b02, b02);

    size_t base = (size_t)plane * (H_HR * W_HR) + (size_t)oy * W_HR;
    float4 xv = reinterpret_cast<const float4*>(xhr + base)[qx];
    float xin[4] = {xv.x, xv.y, xv.z, xv.w};
    float res[4];

    #pragma unroll
    for (int k = 0; k < 4; k++) {
        float posx = (float)(ox0 + k) * SCALE;
        int jx = (int)posx;
        float txf = posx - (float)jx;
        bool hi = (jx > jb);
        float aLo = hi ? Ac1 : Ac0;
        float aHi = hi ? Ac2 : Ac1;
        float bLo = hi ? Bc1 : Bc0;
        float bHi = hi ? Bc2 : Bc1;
        float aV = fmaf(txf, aHi - aLo, aLo);
        float bV = fmaf(txf, bHi - bLo, bLo);
        float r = fmaf(aV, xin[k], bV);
        res[k] = fminf(fmaxf(r, 0.0f), 255.0f);
    }

    float4 ov = make_float4(res[0], res[1], res[2], res[3]);
    reinterpret_cast<float4*>(out + base)[qx] = ov;
}

extern "C" void kernel_launch(void* const* d_in, const int* in_sizes, int n_in,
                              void* d_out, int out_size) {
    const float* x_lr = (const float*)d_in[0];
    const float* y_lr = (const float*)d_in[1];
    const float* x_hr = (const float*)d_in[2];
    float* out = (float*)d_out;

    dim3 g1(W_LR / TILE, H_LR / TILE, PLANES);   // (16,16,12)
    dim3 b1(32, 8);
    k1_ab_mean<<<g1, b1>>>(x_lr, y_lr);

    dim3 g2((W_HR / 4) / 256, H_HR, PLANES);     // (2,2048,12)
    dim3 b2(256);
    k2_upsample_apply<<<g2, b2>>>(x_hr, out);
}